// round 1
// baseline (speedup 1.0000x reference)
#include <cuda_runtime.h>
#include <cuda_bf16.h>

// ---------------------------------------------------------------------------
// MAB: q=Q@Wq+bq; k=K@Wk+bk; v=K@Wv+bv  (heads interleaved: d = h*64+dh)
//      S = (q.k^T)/8 per head, mask==0 -> -1e9, softmax
//      o = q + S@v ; O=LN0(o) ; O = LN1(O + relu(O@Wo + bo))
// B=8, N=1024, D=512, H=8, DH=64
// ---------------------------------------------------------------------------

#define BATCH 8
#define NTOK  1024
#define DMODEL 512
#define NHEAD 8
#define DHEAD 64
#define NROWS (BATCH * NTOK)   // 8192

// scratch (no allocations allowed)
__device__ float g_q[BATCH * NTOK * DMODEL];
__device__ float g_k[BATCH * NTOK * DMODEL];
__device__ float g_v[BATCH * NTOK * DMODEL];
__device__ float g_o[BATCH * NTOK * DMODEL];
__device__ float g_ln0[BATCH * NTOK * DMODEL];
__device__ float g_tmp[BATCH * NTOK * DMODEL];

// ---------------------------------------------------------------------------
// GEMM: C[M,N] = A[M,K] @ B[K,N] + bias[N]  (optional relu)
// Block tile 64x64, BK=16, 256 threads, 4x4 per thread.
// ---------------------------------------------------------------------------
#define GBM 64
#define GBN 64
#define GBK 16

__global__ void gemm_bias_kernel(const float* __restrict__ A,
                                 const float* __restrict__ Bm,
                                 const float* __restrict__ bias,
                                 float* __restrict__ C,
                                 int M, int N, int K, int relu)
{
    __shared__ float sA[GBK][GBM + 4];   // [k][m], padded
    __shared__ float sB[GBK][GBN];       // [k][n]

    int t  = threadIdx.x;                // 0..255
    int bm = blockIdx.y * GBM;
    int bn = blockIdx.x * GBN;
    int tx = t & 15;                     // 0..15
    int ty = t >> 4;                     // 0..15

    float acc[4][4];
#pragma unroll
    for (int i = 0; i < 4; i++)
#pragma unroll
        for (int j = 0; j < 4; j++) acc[i][j] = 0.f;

    for (int k0 = 0; k0 < K; k0 += GBK) {
        // load A tile (64x16) -> sA[k][m]
#pragma unroll
        for (int l = 0; l < 4; l++) {
            int m  = (t >> 4) + 16 * l;
            int kk = t & 15;
            sA[kk][m] = A[(size_t)(bm + m) * K + k0 + kk];
        }
        // load B tile (16x64) -> sB[k][n]
#pragma unroll
        for (int l = 0; l < 4; l++) {
            int idx = t + 256 * l;
            int kk  = idx >> 6;
            int n   = idx & 63;
            sB[kk][n] = Bm[(size_t)(k0 + kk) * N + bn + n];
        }
        __syncthreads();

#pragma unroll
        for (int kk = 0; kk < GBK; kk++) {
            float4 a4 = *(const float4*)&sA[kk][ty * 4];
            float4 b4 = *(const float4*)&sB[kk][tx * 4];
            float a[4] = {a4.x, a4.y, a4.z, a4.w};
            float b[4] = {b4.x, b4.y, b4.z, b4.w};
#pragma unroll
            for (int i = 0; i < 4; i++)
#pragma unroll
                for (int j = 0; j < 4; j++) acc[i][j] += a[i] * b[j];
        }
        __syncthreads();
    }

#pragma unroll
    for (int i = 0; i < 4; i++) {
        int m = bm + ty * 4 + i;
#pragma unroll
        for (int j = 0; j < 4; j++) {
            int n = bn + tx * 4 + j;
            float v = acc[i][j] + bias[n];
            if (relu) v = fmaxf(v, 0.f);
            C[(size_t)m * N + n] = v;
        }
    }
}

// ---------------------------------------------------------------------------
// Attention: one block = (b, h, 16 query rows). Full score row in smem.
// ---------------------------------------------------------------------------
#define TQ 16
#define KC 128
#define QSTRIDE 68      // DHEAD + 4 pad (float4-aligned, breaks bank stride)
#define SSTRIDE 1028    // NTOK + 4 pad

#define ATTN_SMEM ((TQ*QSTRIDE + TQ*SSTRIDE + KC*QSTRIDE + NTOK) * 4)

__global__ void attn_kernel(const float* __restrict__ q,
                            const float* __restrict__ k,
                            const float* __restrict__ v,
                            const int* __restrict__ mask,
                            float* __restrict__ o)
{
    extern __shared__ float sm[];
    float* qs = sm;                          // [TQ][QSTRIDE]
    float* S  = qs + TQ * QSTRIDE;           // [TQ][SSTRIDE]
    float* kv = S + TQ * SSTRIDE;            // [KC][QSTRIDE]
    float* mk = kv + KC * QSTRIDE;           // [NTOK]  1.0 valid / 0.0 masked

    const int t  = threadIdx.x;              // 256
    const int b  = blockIdx.z;
    const int h  = blockIdx.y;
    const int q0 = blockIdx.x * TQ;
    const float scale = 0.125f;              // 1/sqrt(64)

    // load q tile (16 x 64) and mask
    {
        int i  = t >> 4;
        int d0 = (t & 15) * 4;
        *(float4*)&qs[i * QSTRIDE + d0] =
            *(const float4*)&q[((size_t)(b * NTOK + q0 + i)) * DMODEL + h * DHEAD + d0];
    }
    for (int j = t; j < NTOK; j += 256)
        mk[j] = (mask[b * NTOK + j] == 0) ? 0.f : 1.f;

    // ---- scores ----
    for (int kc = 0; kc < NTOK; kc += KC) {
        __syncthreads();
        {   // load k chunk (128 x 64)
            int d0 = (t & 15) * 4;
            int jb = t >> 4;
#pragma unroll
            for (int l = 0; l < 8; l++) {
                int j = jb + l * 16;
                *(float4*)&kv[j * QSTRIDE + d0] =
                    *(const float4*)&k[((size_t)(b * NTOK + kc + j)) * DMODEL + h * DHEAD + d0];
            }
        }
        __syncthreads();
        {   // each thread: 1 row x 8 cols
            int i  = t & 15;
            int jb = (t >> 4) * 8;
            float acc[8] = {0, 0, 0, 0, 0, 0, 0, 0};
#pragma unroll 8
            for (int d = 0; d < DHEAD; d++) {
                float qd = qs[i * QSTRIDE + d];
#pragma unroll
                for (int jj = 0; jj < 8; jj++)
                    acc[jj] += qd * kv[(jb + jj) * QSTRIDE + d];
            }
#pragma unroll
            for (int jj = 0; jj < 8; jj++) {
                int j = kc + jb + jj;
                S[i * SSTRIDE + j] = (mk[j] != 0.f) ? acc[jj] * scale : -1e9f;
            }
        }
    }
    __syncthreads();

    // ---- softmax: warp w handles rows 2w, 2w+1 ----
    {
        int w = t >> 5, lane = t & 31;
#pragma unroll
        for (int r = 0; r < 2; r++) {
            int i = w * 2 + r;
            float mx = -1e30f;
            for (int c = lane; c < NTOK; c += 32) mx = fmaxf(mx, S[i * SSTRIDE + c]);
#pragma unroll
            for (int s2 = 16; s2; s2 >>= 1) mx = fmaxf(mx, __shfl_xor_sync(~0u, mx, s2));
            float sum = 0.f;
            for (int c = lane; c < NTOK; c += 32) {
                float e = __expf(S[i * SSTRIDE + c] - mx);
                S[i * SSTRIDE + c] = e;
                sum += e;
            }
#pragma unroll
            for (int s2 = 16; s2; s2 >>= 1) sum += __shfl_xor_sync(~0u, sum, s2);
            float inv = 1.f / sum;
            for (int c = lane; c < NTOK; c += 32) S[i * SSTRIDE + c] *= inv;
        }
    }

    // ---- O = q + A @ v ----
    {
        int i  = t >> 4;
        int d0 = (t & 15) * 4;
        float4 acc = make_float4(0.f, 0.f, 0.f, 0.f);
        for (int kc = 0; kc < NTOK; kc += KC) {
            __syncthreads();
            {   // load v chunk
                int dd = (t & 15) * 4;
                int jb = t >> 4;
#pragma unroll
                for (int l = 0; l < 8; l++) {
                    int j = jb + l * 16;
                    *(float4*)&kv[j * QSTRIDE + dd] =
                        *(const float4*)&v[((size_t)(b * NTOK + kc + j)) * DMODEL + h * DHEAD + dd];
                }
            }
            __syncthreads();
#pragma unroll 4
            for (int j = 0; j < KC; j++) {
                float a = S[i * SSTRIDE + kc + j];
                float4 vv = *(float4*)&kv[j * QSTRIDE + d0];
                acc.x += a * vv.x;
                acc.y += a * vv.y;
                acc.z += a * vv.z;
                acc.w += a * vv.w;
            }
        }
        float4 qv = *(float4*)&qs[i * QSTRIDE + d0];
        acc.x += qv.x; acc.y += qv.y; acc.z += qv.z; acc.w += qv.w;
        *(float4*)&o[((size_t)(b * NTOK + q0 + i)) * DMODEL + h * DHEAD + d0] = acc;
    }
}

// ---------------------------------------------------------------------------
// LayerNorm over 512 (optionally x = x1 + x2 first). 128 threads per row.
// ---------------------------------------------------------------------------
__global__ void ln_kernel(const float* __restrict__ x1,
                          const float* __restrict__ x2,
                          const float* __restrict__ g,
                          const float* __restrict__ bb,
                          float* __restrict__ y)
{
    __shared__ float ws[4], ws2[4];
    int row = blockIdx.x;
    int t   = threadIdx.x;          // 128
    int c0  = t * 4;

    float4 xv = *(const float4*)&x1[(size_t)row * DMODEL + c0];
    if (x2) {
        float4 a = *(const float4*)&x2[(size_t)row * DMODEL + c0];
        xv.x += a.x; xv.y += a.y; xv.z += a.z; xv.w += a.w;
    }
    float s = xv.x + xv.y + xv.z + xv.w;
#pragma unroll
    for (int o = 16; o; o >>= 1) s += __shfl_xor_sync(~0u, s, o);
    if ((t & 31) == 0) ws[t >> 5] = s;
    __syncthreads();
    float mean = (ws[0] + ws[1] + ws[2] + ws[3]) * (1.f / DMODEL);

    float dx = xv.x - mean, dy = xv.y - mean, dz = xv.z - mean, dw = xv.w - mean;
    float s2 = dx * dx + dy * dy + dz * dz + dw * dw;
#pragma unroll
    for (int o = 16; o; o >>= 1) s2 += __shfl_xor_sync(~0u, s2, o);
    if ((t & 31) == 0) ws2[t >> 5] = s2;
    __syncthreads();
    float var = (ws2[0] + ws2[1] + ws2[2] + ws2[3]) * (1.f / DMODEL);
    float inv = rsqrtf(var + 1e-5f);

    float4 gv = *(const float4*)&g[c0];
    float4 bv = *(const float4*)&bb[c0];
    float4 yv;
    yv.x = dx * inv * gv.x + bv.x;
    yv.y = dy * inv * gv.y + bv.y;
    yv.z = dz * inv * gv.z + bv.z;
    yv.w = dw * inv * gv.w + bv.w;
    *(float4*)&y[(size_t)row * DMODEL + c0] = yv;
}

// ---------------------------------------------------------------------------
extern "C" void kernel_launch(void* const* d_in, const int* in_sizes, int n_in,
                              void* d_out, int out_size)
{
    const float* Q    = (const float*)d_in[0];
    const float* K    = (const float*)d_in[1];
    const int*   mask = (const int*)  d_in[2];
    const float* Wq   = (const float*)d_in[3];
    const float* bq   = (const float*)d_in[4];
    const float* Wk   = (const float*)d_in[5];
    const float* bk   = (const float*)d_in[6];
    const float* Wv   = (const float*)d_in[7];
    const float* bv   = (const float*)d_in[8];
    const float* Wo   = (const float*)d_in[9];
    const float* bo   = (const float*)d_in[10];
    const float* g0   = (const float*)d_in[11];
    const float* b0   = (const float*)d_in[12];
    const float* g1   = (const float*)d_in[13];
    const float* b1   = (const float*)d_in[14];

    float *gq, *gk, *gv, *go, *gl, *gt;
    cudaGetSymbolAddress((void**)&gq, g_q);
    cudaGetSymbolAddress((void**)&gk, g_k);
    cudaGetSymbolAddress((void**)&gv, g_v);
    cudaGetSymbolAddress((void**)&go, g_o);
    cudaGetSymbolAddress((void**)&gl, g_ln0);
    cudaGetSymbolAddress((void**)&gt, g_tmp);

    dim3 ggrid(DMODEL / GBN, NROWS / GBM);   // (8, 128)

    gemm_bias_kernel<<<ggrid, 256>>>(Q, Wq, bq, gq, NROWS, DMODEL, DMODEL, 0);
    gemm_bias_kernel<<<ggrid, 256>>>(K, Wk, bk, gk, NROWS, DMODEL, DMODEL, 0);
    gemm_bias_kernel<<<ggrid, 256>>>(K, Wv, bv, gv, NROWS, DMODEL, DMODEL, 0);

    cudaFuncSetAttribute(attn_kernel, cudaFuncAttributeMaxDynamicSharedMemorySize,
                         ATTN_SMEM);
    attn_kernel<<<dim3(NTOK / TQ, NHEAD, BATCH), 256, ATTN_SMEM>>>(gq, gk, gv, mask, go);

    ln_kernel<<<NROWS, 128>>>(go, nullptr, g0, b0, gl);
    gemm_bias_kernel<<<ggrid, 256>>>(gl, Wo, bo, gt, NROWS, DMODEL, DMODEL, 1);
    ln_kernel<<<NROWS, 128>>>(gl, gt, g1, b1, (float*)d_out);
}

// round 2
// speedup vs baseline: 1.6289x; 1.6289x over previous
#include <cuda_runtime.h>
#include <cuda_bf16.h>

// ---------------------------------------------------------------------------
// MAB: q=Q@Wq+bq; k=K@Wk+bk; v=K@Wv+bv  (heads interleaved: d = h*64+dh)
//      S = (q.k^T)/8 per head, mask==0 -> -1e9, softmax (flash/online)
//      o = q + S@v ; O=LN0(o) ; O = LN1(O + relu(O@Wo + bo))
// B=8, N=1024, D=512, H=8, DH=64.  All math fp32 via packed f32x2 FFMA.
// ---------------------------------------------------------------------------

#define BATCH 8
#define NTOK  1024
#define DMODEL 512
#define NHEAD 8
#define DHEAD 64
#define NROWS (BATCH * NTOK)   // 8192

typedef unsigned long long u64;

__device__ __forceinline__ void ffma2(u64& d, u64 a, u64 b) {
    asm("fma.rn.f32x2 %0, %1, %2, %0;" : "+l"(d) : "l"(a), "l"(b));
}
__device__ __forceinline__ u64 pk2(float x, float y) {
    u64 r; asm("mov.b64 %0, {%1, %2};" : "=l"(r) : "f"(x), "f"(y)); return r;
}
__device__ __forceinline__ float2 up2(u64 v) {
    float2 r; asm("mov.b64 {%0, %1}, %2;" : "=f"(r.x), "=f"(r.y) : "l"(v)); return r;
}
__device__ __forceinline__ void fmul2_(u64& d, u64 a) {
    asm("mul.rn.f32x2 %0, %0, %1;" : "+l"(d) : "l"(a));
}

// scratch (no allocations allowed)
__device__ float g_q[BATCH * NTOK * DMODEL];
__device__ float g_k[BATCH * NTOK * DMODEL];
__device__ float g_v[BATCH * NTOK * DMODEL];
__device__ float g_o[BATCH * NTOK * DMODEL];
__device__ float g_ln0[BATCH * NTOK * DMODEL];
__device__ float g_tmp[BATCH * NTOK * DMODEL];

// ---------------------------------------------------------------------------
// GEMM: C[M,N] = A[M,K] @ B[K,N] + bias[N]  (optional relu)
// Block tile 128x64, BK=16, 256 threads, 8x4 per thread, f32x2 packed FMA.
// ---------------------------------------------------------------------------
#define GBM 128
#define GBN 64
#define GBK 16
#define SASTR (GBM + 4)   // 132 floats (16B multiple)
#define SBSTR (GBN + 4)   // 68 floats

__global__ __launch_bounds__(256) void gemm_bias_kernel(
    const float* __restrict__ A, const float* __restrict__ Bm,
    const float* __restrict__ bias, float* __restrict__ C,
    int M, int N, int K, int relu)
{
    __shared__ __align__(16) float sA[GBK][SASTR];   // [k][m]
    __shared__ __align__(16) float sB[GBK][SBSTR];   // [k][n]

    const int t  = threadIdx.x;
    const int bm = blockIdx.y * GBM;
    const int bn = blockIdx.x * GBN;
    const int tx = t & 15;     // col group: 4 cols
    const int ty = t >> 4;     // row group: 8 rows (4 pairs)

    u64 acc[4][4];
#pragma unroll
    for (int p = 0; p < 4; p++)
#pragma unroll
        for (int j = 0; j < 4; j++) acc[p][j] = 0ull;

    for (int k0 = 0; k0 < K; k0 += GBK) {
        // A tile 128x16 -> sA[k][m] (transposed)
#pragma unroll
        for (int l = 0; l < 2; l++) {
            int r = (t >> 2) + (l << 6);
            int c = (t & 3) << 2;
            float4 av = *(const float4*)&A[(size_t)(bm + r) * K + k0 + c];
            sA[c + 0][r] = av.x; sA[c + 1][r] = av.y;
            sA[c + 2][r] = av.z; sA[c + 3][r] = av.w;
        }
        // B tile 16x64 -> sB[k][n]
        {
            int kk = t >> 4;
            int n  = (t & 15) << 2;
            *(float4*)&sB[kk][n] = *(const float4*)&Bm[(size_t)(k0 + kk) * N + bn + n];
        }
        __syncthreads();

#pragma unroll
        for (int kk = 0; kk < GBK; kk++) {
            const u64* ap = (const u64*)&sA[kk][ty << 3];   // 4 row pairs
            u64 a0 = ap[0], a1 = ap[1], a2 = ap[2], a3 = ap[3];
            float4 bv = *(const float4*)&sB[kk][tx << 2];
            u64 b0 = pk2(bv.x, bv.x), b1 = pk2(bv.y, bv.y);
            u64 b2 = pk2(bv.z, bv.z), b3 = pk2(bv.w, bv.w);
            ffma2(acc[0][0], a0, b0); ffma2(acc[0][1], a0, b1);
            ffma2(acc[0][2], a0, b2); ffma2(acc[0][3], a0, b3);
            ffma2(acc[1][0], a1, b0); ffma2(acc[1][1], a1, b1);
            ffma2(acc[1][2], a1, b2); ffma2(acc[1][3], a1, b3);
            ffma2(acc[2][0], a2, b0); ffma2(acc[2][1], a2, b1);
            ffma2(acc[2][2], a2, b2); ffma2(acc[2][3], a2, b3);
            ffma2(acc[3][0], a3, b0); ffma2(acc[3][1], a3, b1);
            ffma2(acc[3][2], a3, b2); ffma2(acc[3][3], a3, b3);
        }
        __syncthreads();
    }

    float4 bs = *(const float4*)&bias[bn + (tx << 2)];
#pragma unroll
    for (int p = 0; p < 4; p++) {
        float4 r0, r1; float2 u;
        u = up2(acc[p][0]); r0.x = u.x + bs.x; r1.x = u.y + bs.x;
        u = up2(acc[p][1]); r0.y = u.x + bs.y; r1.y = u.y + bs.y;
        u = up2(acc[p][2]); r0.z = u.x + bs.z; r1.z = u.y + bs.z;
        u = up2(acc[p][3]); r0.w = u.x + bs.w; r1.w = u.y + bs.w;
        if (relu) {
            r0.x = fmaxf(r0.x, 0.f); r0.y = fmaxf(r0.y, 0.f);
            r0.z = fmaxf(r0.z, 0.f); r0.w = fmaxf(r0.w, 0.f);
            r1.x = fmaxf(r1.x, 0.f); r1.y = fmaxf(r1.y, 0.f);
            r1.z = fmaxf(r1.z, 0.f); r1.w = fmaxf(r1.w, 0.f);
        }
        int row = bm + (ty << 3) + (p << 1);
        *(float4*)&C[(size_t)row * N + bn + (tx << 2)]       = r0;
        *(float4*)&C[(size_t)(row + 1) * N + bn + (tx << 2)] = r1;
    }
}

// ---------------------------------------------------------------------------
// Flash attention: block = (b, h, 64 query rows). Online softmax, KC=64 chunks.
// Row group = half-warp (16 threads, same ty) -> warp-sync row stats & P tile.
// ---------------------------------------------------------------------------
#define TQ 64
#define KC 64
#define STR 68

#define ATTN_SMEM ((4 * 64 * STR + NTOK + 2 * TQ) * 4)

__global__ __launch_bounds__(256) void attn_kernel(
    const float* __restrict__ q, const float* __restrict__ k,
    const float* __restrict__ v, const int* __restrict__ mask,
    float* __restrict__ o)
{
    extern __shared__ __align__(16) float sm[];
    float* sQ   = sm;                 // [DH][STR]  q transposed: sQ[d*STR + i]
    float* sK   = sQ + 64 * STR;      // [DH][STR]  k transposed: sK[d*STR + j]
    float* sV   = sK + 64 * STR;      // [KC][STR]  v natural:    sV[j*STR + d]
    float* sP   = sV + 64 * STR;      // [TQ][STR]  probs:        sP[i*STR + j]
    float* mk   = sP + 64 * STR;      // [NTOK]  1.0 valid / 0.0 masked
    float* mrun = mk + NTOK;          // [TQ] running max
    float* lrun = mrun + TQ;          // [TQ] running sum

    const int t  = threadIdx.x;       // 256
    const int b  = blockIdx.z;
    const int h  = blockIdx.y;
    const int q0 = blockIdx.x * TQ;
    const int tx = t & 15;
    const int ty = t >> 4;
    const int i0 = ty << 2;           // 4 rows owned (both phases)
    const int j0 = tx << 2;           // phase-1: 4 score cols
    const int d0 = tx << 2;           // phase-2: 4 head dims

    // load Q tile transposed + mask + stats init
#pragma unroll
    for (int l = 0; l < 4; l++) {
        int idx = t + (l << 8);
        int i   = idx >> 4;
        int dd  = (idx & 15) << 2;
        float4 qv = *(const float4*)&q[((size_t)(b * NTOK + q0 + i)) * DMODEL + h * DHEAD + dd];
        sQ[(dd + 0) * STR + i] = qv.x; sQ[(dd + 1) * STR + i] = qv.y;
        sQ[(dd + 2) * STR + i] = qv.z; sQ[(dd + 3) * STR + i] = qv.w;
    }
    for (int j = t; j < NTOK; j += 256)
        mk[j] = (mask[b * NTOK + j] == 0) ? 0.f : 1.f;
    if (t < TQ) { mrun[t] = -1e30f; lrun[t] = 0.f; }

    u64 o2[4][2];                     // O acc: 4 rows x 2 d-pairs (packed along d)
#pragma unroll
    for (int ii = 0; ii < 4; ii++) { o2[ii][0] = 0ull; o2[ii][1] = 0ull; }

    for (int kc = 0; kc < NTOK; kc += KC) {
        __syncthreads();              // prev phase-2 readers done
        // load K chunk transposed + V chunk natural
#pragma unroll
        for (int l = 0; l < 4; l++) {
            int idx = t + (l << 8);
            int j   = idx >> 4;
            int dd  = (idx & 15) << 2;
            size_t base = ((size_t)(b * NTOK + kc + j)) * DMODEL + h * DHEAD + dd;
            float4 kv4 = *(const float4*)&k[base];
            sK[(dd + 0) * STR + j] = kv4.x; sK[(dd + 1) * STR + j] = kv4.y;
            sK[(dd + 2) * STR + j] = kv4.z; sK[(dd + 3) * STR + j] = kv4.w;
            *(float4*)&sV[j * STR + dd] = *(const float4*)&v[base];
        }
        __syncthreads();

        // ---- phase 1: S = q.k^T (4x4 tile, packed along i) ----
        u64 sp[2][4];
#pragma unroll
        for (int p = 0; p < 2; p++)
#pragma unroll
            for (int j = 0; j < 4; j++) sp[p][j] = 0ull;

#pragma unroll 8
        for (int d = 0; d < DHEAD; d++) {
            ulonglong2 qp = *(const ulonglong2*)&sQ[d * STR + i0];   // rows i0..i0+3
            float4 kv4 = *(const float4*)&sK[d * STR + j0];
            u64 k0p = pk2(kv4.x, kv4.x), k1p = pk2(kv4.y, kv4.y);
            u64 k2p = pk2(kv4.z, kv4.z), k3p = pk2(kv4.w, kv4.w);
            ffma2(sp[0][0], qp.x, k0p); ffma2(sp[0][1], qp.x, k1p);
            ffma2(sp[0][2], qp.x, k2p); ffma2(sp[0][3], qp.x, k3p);
            ffma2(sp[1][0], qp.y, k0p); ffma2(sp[1][1], qp.y, k1p);
            ffma2(sp[1][2], qp.y, k2p); ffma2(sp[1][3], qp.y, k3p);
        }

        // unpack to sv_[ii][jj]
        float sv_[4][4];
#pragma unroll
        for (int p = 0; p < 2; p++)
#pragma unroll
            for (int j = 0; j < 4; j++) {
                float2 u = up2(sp[p][j]);
                sv_[2 * p + 0][j] = u.x;
                sv_[2 * p + 1][j] = u.y;
            }
        float fl[4];
#pragma unroll
        for (int jj = 0; jj < 4; jj++) fl[jj] = mk[kc + j0 + jj];

        float al[4];
#pragma unroll
        for (int ii = 0; ii < 4; ii++) {
            float s0 = (fl[0] != 0.f) ? sv_[ii][0] * 0.125f : -1e9f;
            float s1 = (fl[1] != 0.f) ? sv_[ii][1] * 0.125f : -1e9f;
            float s2 = (fl[2] != 0.f) ? sv_[ii][2] * 0.125f : -1e9f;
            float s3 = (fl[3] != 0.f) ? sv_[ii][3] * 0.125f : -1e9f;
            float rmx = fmaxf(fmaxf(s0, s1), fmaxf(s2, s3));
#pragma unroll
            for (int off = 8; off; off >>= 1)
                rmx = fmaxf(rmx, __shfl_xor_sync(0xffffffffu, rmx, off));
            int i = i0 + ii;
            float mold = mrun[i];
            float mnew = fmaxf(mold, rmx);
            float a    = __expf(mold - mnew);
            float p0 = __expf(s0 - mnew), p1 = __expf(s1 - mnew);
            float p2 = __expf(s2 - mnew), p3 = __expf(s3 - mnew);
            float rs = (p0 + p1) + (p2 + p3);
#pragma unroll
            for (int off = 8; off; off >>= 1)
                rs += __shfl_xor_sync(0xffffffffu, rs, off);
            if (tx == 0) { mrun[i] = mnew; lrun[i] = lrun[i] * a + rs; }
            al[ii] = a;
            *(float4*)&sP[i * STR + j0] = make_float4(p0, p1, p2, p3);
        }
        __syncwarp();   // sP rows / stats visible within half-warp row groups

        // ---- phase 2: O = O*alpha + P @ V (packed along d) ----
#pragma unroll
        for (int ii = 0; ii < 4; ii++) {
            u64 ap = pk2(al[ii], al[ii]);
            fmul2_(o2[ii][0], ap);
            fmul2_(o2[ii][1], ap);
        }
#pragma unroll 4
        for (int j = 0; j < KC; j++) {
            ulonglong2 vv = *(const ulonglong2*)&sV[j * STR + d0];   // 2 d-pairs
#pragma unroll
            for (int ii = 0; ii < 4; ii++) {
                float pv = sP[(i0 + ii) * STR + j];    // broadcast within half-warp
                u64 pp = pk2(pv, pv);
                ffma2(o2[ii][0], pp, vv.x);
                ffma2(o2[ii][1], pp, vv.y);
            }
        }
    }

    // ---- final: normalize, add residual q, store ----
#pragma unroll
    for (int ii = 0; ii < 4; ii++) {
        int i = i0 + ii;
        float inv = 1.f / lrun[i];
        float2 u0 = up2(o2[ii][0]);
        float2 u1 = up2(o2[ii][1]);
        float4 res;
        res.x = u0.x * inv + sQ[(d0 + 0) * STR + i];
        res.y = u0.y * inv + sQ[(d0 + 1) * STR + i];
        res.z = u1.x * inv + sQ[(d0 + 2) * STR + i];
        res.w = u1.y * inv + sQ[(d0 + 3) * STR + i];
        *(float4*)&o[((size_t)(b * NTOK + q0 + i)) * DMODEL + h * DHEAD + d0] = res;
    }
}

// ---------------------------------------------------------------------------
// LayerNorm over 512 (optionally x = x1 + x2 first). 128 threads per row.
// ---------------------------------------------------------------------------
__global__ void ln_kernel(const float* __restrict__ x1,
                          const float* __restrict__ x2,
                          const float* __restrict__ g,
                          const float* __restrict__ bb,
                          float* __restrict__ y)
{
    __shared__ float ws[4], ws2[4];
    int row = blockIdx.x;
    int t   = threadIdx.x;          // 128
    int c0  = t * 4;

    float4 xv = *(const float4*)&x1[(size_t)row * DMODEL + c0];
    if (x2) {
        float4 a = *(const float4*)&x2[(size_t)row * DMODEL + c0];
        xv.x += a.x; xv.y += a.y; xv.z += a.z; xv.w += a.w;
    }
    float s = xv.x + xv.y + xv.z + xv.w;
#pragma unroll
    for (int o = 16; o; o >>= 1) s += __shfl_xor_sync(~0u, s, o);
    if ((t & 31) == 0) ws[t >> 5] = s;
    __syncthreads();
    float mean = (ws[0] + ws[1] + ws[2] + ws[3]) * (1.f / DMODEL);

    float dx = xv.x - mean, dy = xv.y - mean, dz = xv.z - mean, dw = xv.w - mean;
    float s2 = dx * dx + dy * dy + dz * dz + dw * dw;
#pragma unroll
    for (int o = 16; o; o >>= 1) s2 += __shfl_xor_sync(~0u, s2, o);
    if ((t & 31) == 0) ws2[t >> 5] = s2;
    __syncthreads();
    float var = (ws2[0] + ws2[1] + ws2[2] + ws2[3]) * (1.f / DMODEL);
    float inv = rsqrtf(var + 1e-5f);

    float4 gv = *(const float4*)&g[c0];
    float4 bv = *(const float4*)&bb[c0];
    float4 yv;
    yv.x = dx * inv * gv.x + bv.x;
    yv.y = dy * inv * gv.y + bv.y;
    yv.z = dz * inv * gv.z + bv.z;
    yv.w = dw * inv * gv.w + bv.w;
    *(float4*)&y[(size_t)row * DMODEL + c0] = yv;
}

// ---------------------------------------------------------------------------
extern "C" void kernel_launch(void* const* d_in, const int* in_sizes, int n_in,
                              void* d_out, int out_size)
{
    const float* Q    = (const float*)d_in[0];
    const float* K    = (const float*)d_in[1];
    const int*   mask = (const int*)  d_in[2];
    const float* Wq   = (const float*)d_in[3];
    const float* bq   = (const float*)d_in[4];
    const float* Wk   = (const float*)d_in[5];
    const float* bk   = (const float*)d_in[6];
    const float* Wv   = (const float*)d_in[7];
    const float* bv   = (const float*)d_in[8];
    const float* Wo   = (const float*)d_in[9];
    const float* bo   = (const float*)d_in[10];
    const float* g0   = (const float*)d_in[11];
    const float* b0   = (const float*)d_in[12];
    const float* g1   = (const float*)d_in[13];
    const float* b1   = (const float*)d_in[14];

    float *gq, *gk, *gv, *go, *gl, *gt;
    cudaGetSymbolAddress((void**)&gq, g_q);
    cudaGetSymbolAddress((void**)&gk, g_k);
    cudaGetSymbolAddress((void**)&gv, g_v);
    cudaGetSymbolAddress((void**)&go, g_o);
    cudaGetSymbolAddress((void**)&gl, g_ln0);
    cudaGetSymbolAddress((void**)&gt, g_tmp);

    dim3 ggrid(DMODEL / GBN, NROWS / GBM);   // (8, 64)

    gemm_bias_kernel<<<ggrid, 256>>>(Q, Wq, bq, gq, NROWS, DMODEL, DMODEL, 0);
    gemm_bias_kernel<<<ggrid, 256>>>(K, Wk, bk, gk, NROWS, DMODEL, DMODEL, 0);
    gemm_bias_kernel<<<ggrid, 256>>>(K, Wv, bv, gv, NROWS, DMODEL, DMODEL, 0);

    cudaFuncSetAttribute(attn_kernel, cudaFuncAttributeMaxDynamicSharedMemorySize,
                         ATTN_SMEM);
    attn_kernel<<<dim3(NTOK / TQ, NHEAD, BATCH), 256, ATTN_SMEM>>>(gq, gk, gv, mask, go);

    ln_kernel<<<NROWS, 128>>>(go, nullptr, g0, b0, gl);
    gemm_bias_kernel<<<ggrid, 256>>>(gl, Wo, bo, gt, NROWS, DMODEL, DMODEL, 1);
    ln_kernel<<<NROWS, 128>>>(gl, gt, g1, b1, (float*)d_out);
}